// round 15
// baseline (speedup 1.0000x reference)
#include <cuda_runtime.h>
#include <cstdint>

// ---------------------------------------------------------------------------
// fp4 (bitsandbytes) dequant + GEMV:  y[4, M] = x[4, N] @ W[M, N]^T + bias
//   qweight: numel/2 int32, each holding ONE byte (two nibbles, hi first)
//   absmax : per-64-element block scale; code: 16-entry codebook
//
// Mapping: warp owns a contiguous 64-n "step"; lane l takes the packed byte
// at int32 index (step*32 + l), i.e. n = 2l, 2l+1.
// R15 changes vs R14:
//   * q: L2 prefetch at distance 4 (1 predicated instr/step, lanes 0-3) so
//     the distance-1 register prefetch LDG hits L2 (~250cyc) not DRAM.
//   * absmax relayout [step][row-in-block] -> one LDS.128 per step.
//   * x staged as interleaved {even,odd} ulonglong2 -> two LDS.128 per step.
// Epilogue: out zeroed by cudaMemsetAsync; 2 commutative atomicAdds per
// output (bit-deterministic); bias folded into split 0.
// grid (2,512)=1024 blocks x 128 thr, 7 CTAs/SM -> single wave.
// ---------------------------------------------------------------------------

constexpr int MD = 8192, ND = 8192;
constexpr int NSPLIT = 2;
constexpr int NHALF  = ND / NSPLIT;       // 4096 n per block
constexpr int CHALF  = NHALF / 2;         // 2048 int32 cols per row-half
constexpr int STEPS  = CHALF / 32;        // 64 steps (one absmax block each)
constexpr int RW = 4;                     // rows per warp
constexpr int WPB = 4;                    // warps per block (128 threads)
constexpr int RPB = RW * WPB;             // 16 rows per block
constexpr int PH_COLS = 512;              // staged cols per phase (16 KB)
constexpr int PHASES  = CHALF / PH_COLS;  // 4
constexpr int SPP     = PH_COLS / 32;     // 16 steps per phase
constexpr int PFD     = 4 * 32;           // L2 prefetch distance (4 steps)

static __device__ __forceinline__ unsigned long long pk2(float lo, float hi) {
    unsigned long long r;
    asm("mov.b64 %0, {%1, %2};" : "=l"(r) : "f"(lo), "f"(hi));
    return r;
}
static __device__ __forceinline__ void up2(unsigned long long v, float& lo, float& hi) {
    asm("mov.b64 {%0, %1}, %2;" : "=f"(lo), "=f"(hi) : "l"(v));
}
static __device__ __forceinline__ unsigned long long f2fma(unsigned long long a,
                                                           unsigned long long b,
                                                           unsigned long long c) {
    unsigned long long d;
    asm("fma.rn.f32x2 %0, %1, %2, %3;" : "=l"(d) : "l"(a), "l"(b), "l"(c));
    return d;
}
static __device__ __forceinline__ unsigned long long f2add(unsigned long long a,
                                                           unsigned long long b) {
    unsigned long long d;
    asm("add.rn.f32x2 %0, %1, %2;" : "=l"(d) : "l"(a), "l"(b));
    return d;
}

__global__ void __launch_bounds__(128, 7)
fp4_main(const float* __restrict__ x, const int* __restrict__ qw,
         const float* __restrict__ am, const float* __restrict__ code,
         const float* __restrict__ bias, float* __restrict__ out)
{
    __shared__ float am_sm[STEPS * RPB];                  // [step][row], 4 KB
    __shared__ ulonglong2 x01_sm[PH_COLS];                // {xe01, xo01}, 8 KB
    __shared__ ulonglong2 x23_sm[PH_COLS];                // {xe23, xo23}, 8 KB

    const int lane = threadIdx.x & 31;
    const int wid  = threadIdx.x >> 5;
    const int split   = blockIdx.x;            // 0 or 1
    const int rowbase = blockIdx.y * RPB;
    const int row0    = rowbase + wid * RW;
    const int n0      = split * NHALF;

    // Register-resident codebook: lane l holds code[l & 15]; decode via shfl.
    const float creg = code[lane & 15];

    // ---- absmax preload, transposed to [step][row]: gmem-coalesced reads ----
    for (int k = threadIdx.x; k < RPB * STEPS; k += 128) {
        const int r  = k >> 6;          // row in block
        const int st = k & 63;          // step
        am_sm[st * RPB + r] = am[(rowbase + r) * (ND / 64) + split * (NHALF / 64) + st];
    }

    // Per-row q streams for this N-half.
    const int* q0 = qw + row0 * (ND / 2) + split * CHALF;
    const float2* x0 = reinterpret_cast<const float2*>(x + 0 * ND + n0);
    const float2* x1 = reinterpret_cast<const float2*>(x + 1 * ND + n0);
    const float2* x2 = reinterpret_cast<const float2*>(x + 2 * ND + n0);
    const float2* x3 = reinterpret_cast<const float2*>(x + 3 * ND + n0);

    unsigned long long a01[RW] = {0, 0, 0, 0};
    unsigned long long a23[RW] = {0, 0, 0, 0};

    // ---- q prefetch, distance 1 (registers) ----
    int bq[RW];
#pragma unroll
    for (int r = 0; r < RW; r++) bq[r] = __ldcs(q0 + r * (ND / 2) + lane);

    for (int ph = 0; ph < PHASES; ++ph) {
        // ---- stage this phase's x cols in interleaved batch-pair form ----
        const int cbase = ph * PH_COLS;
#pragma unroll
        for (int kk = 0; kk < PH_COLS / 128; ++kk) {
            const int k = kk * 128 + threadIdx.x;
            const int c = cbase + k;
            const float2 v0 = x0[c];
            const float2 v1 = x1[c];
            const float2 v2 = x2[c];
            const float2 v3 = x3[c];
            x01_sm[k] = make_ulonglong2(pk2(v0.x, v1.x), pk2(v0.y, v1.y));
            x23_sm[k] = make_ulonglong2(pk2(v2.x, v3.x), pk2(v2.y, v3.y));
        }
        __syncthreads();   // x phase (and, on ph==0, am_sm) ready

#pragma unroll 2
        for (int t = 0; t < SPP; ++t) {
            const int step = ph * SPP + t;
            const int col  = step * 32 + lane;

            // L2 prefetch, distance 4: lanes 0..3 prefetch their row's line.
            {
                int pc = col + PFD;
                if (pc >= CHALF) pc = col;            // tail: harmless re-touch
                if (lane < RW) {
                    asm volatile("prefetch.global.L2 [%0];"
                                 :: "l"(q0 + lane * (ND / 2) + pc - lane + (threadIdx.x & 3) * 0));
                }
            }

            // Register prefetch of next step's q bytes (clamped on last step).
            const int ncol = (step < STEPS - 1 ? step + 1 : step) * 32 + lane;
            int bn[RW];
#pragma unroll
            for (int r = 0; r < RW; r++) bn[r] = __ldcs(q0 + r * (ND / 2) + ncol);

            const int k = t * 32 + lane;
            const ulonglong2 p01 = x01_sm[k];   // LDS.128, conflict-free
            const ulonglong2 p23 = x23_sm[k];
            // Per-step scales: 4 consecutive floats -> one LDS.128.
            const float4 sv = *reinterpret_cast<const float4*>(
                                  &am_sm[step * RPB + wid * RW]);
            const float sArr[4] = { sv.x, sv.y, sv.z, sv.w };

#pragma unroll
            for (int r = 0; r < RW; r++) {
                const int   b = bq[r];                 // one byte
                const float s = sArr[r];
                const float chi = __shfl_sync(0xffffffffu, creg, b >> 4);   // n=2l
                const float clo = __shfl_sync(0xffffffffu, creg, b & 15);   // n=2l+1
                const float w0 = chi * s;
                const float w1 = clo * s;
                const unsigned long long s0 = pk2(w0, w0);
                const unsigned long long s1 = pk2(w1, w1);
                a01[r] = f2fma(s0, p01.x, a01[r]);
                a01[r] = f2fma(s1, p01.y, a01[r]);
                a23[r] = f2fma(s0, p23.x, a23[r]);
                a23[r] = f2fma(s1, p23.y, a23[r]);
            }

#pragma unroll
            for (int r = 0; r < RW; r++) bq[r] = bn[r];
        }
        __syncthreads();   // all warps done with this phase before restage
    }

    // Butterfly reduction over lanes (packed f32x2 adds).
#pragma unroll
    for (int r = 0; r < RW; r++) {
#pragma unroll
        for (int off = 16; off > 0; off >>= 1) {
            a01[r] = f2add(a01[r], __shfl_xor_sync(0xffffffffu, a01[r], off));
            a23[r] = f2add(a23[r], __shfl_xor_sync(0xffffffffu, a23[r], off));
        }
    }

    // Accumulate into out (zeroed by the memset graph node). Exactly two
    // commutative IEEE adds per output -> bit-deterministic. Bias once (split 0).
#pragma unroll
    for (int r = 0; r < RW; r++) {
        if (lane == r) {
            const int row = row0 + r;
            float y0, y1, y2, y3;
            up2(a01[r], y0, y1);
            up2(a23[r], y2, y3);
            if (split == 0) {
                const float bb = bias[row];
                y0 += bb; y1 += bb; y2 += bb; y3 += bb;
            }
            atomicAdd(&out[0 * MD + row], y0);
            atomicAdd(&out[1 * MD + row], y1);
            atomicAdd(&out[2 * MD + row], y2);
            atomicAdd(&out[3 * MD + row], y3);
        }
    }
}

extern "C" void kernel_launch(void* const* d_in, const int* in_sizes, int n_in,
                              void* d_out, int out_size)
{
    const float* x    = (const float*)d_in[0];
    const int*   qw   = (const int*)d_in[1];
    const float* am   = (const float*)d_in[2];
    const float* code = (const float*)d_in[3];
    const float* bias = (const float*)d_in[4];
    float*       out  = (float*)d_out;

    cudaMemsetAsync(out, 0, (size_t)out_size * sizeof(float));
    dim3 grid(NSPLIT, MD / RPB);              // (2, 512) = 1024 blocks
    fp4_main<<<grid, WPB * 32>>>(x, qw, am, code, bias, out);
}